// round 10
// baseline (speedup 1.0000x reference)
#include <cuda_runtime.h>
#include <cuda_fp16.h>
#include <cstdint>
#include <cstddef>

// ============================================================================
// WaveletBasis: out[B,O] = haar_basis(x).coeffs + x @ base_weight ; kl = 0
//   B=32768, F=1024, O=64, NB=8
// One fp16 GEMM:  out = A[B,8192] * Bm[8192,64] + bias
//   mma.sync m16n8k16 with FP16 accumulation inside each K=64 chunk (full-rate
//   HMMA), promoted to fp32 accumulators once per chunk. tcgen05 unavailable
//   (harness ptxas targets sm_103 without the 'a' feature set).
// Per feature f (8 K-slots), j = clip(floor(8u),0,7), u=(tanh x+1)/2:
//   A slots = [x, s0, s1, s0s1, s2, s1s2, s0s2, s0s1s2]  (signs from bits of j)
//   Bm rows = [bw, c1, R(c2+c3), R(c2-c3), H4-rotated c4..c7 / 2], R=sqrt2/2
//   bias[o] = sum_f coeffs[f,o,0]
// j computed WITHOUT tanh: u >= i/8  <=>  x >= atanh(i/4 - 1).
// ============================================================================

static constexpr int FDIM = 1024;
static constexpr int NCHUNK = 128;           // K chunks of 64 (8 features)
static constexpr int OUT_ELEMS = 32768 * 64;

#define T1 (-0.9729550745276566f)
#define T2 (-0.5493061443340548f)
#define T3 (-0.2554128118829953f)
#define T5 ( 0.2554128118829953f)
#define T6 ( 0.5493061443340548f)
#define T7 ( 0.9729550745276566f)

// B operand fp16, linear chunk layout: [kt=128][n=64][kp=8] uint4 = 1 MB
__device__ uint4 g_B4[NCHUNK * 512];
__device__ float g_bias[64];

// ---------------------------------------------------------------------------
// Prologue 1: rotated B matrix (fp16)
// ---------------------------------------------------------------------------
__global__ void wb_prep_B(const float* __restrict__ coeffs,
                          const float* __restrict__ bw) {
    int gid = blockIdx.x * blockDim.x + threadIdx.x;   // 65536 = F*O
    int f = gid >> 6;
    int o = gid & 63;
    const float* c = coeffs + (size_t)(f * 64 + o) * 8;
    float c1 = c[1], c2 = c[2], c3 = c[3];
    float c4 = c[4], c5 = c[5], c6 = c[6], c7 = c[7];
    float w = bw[f * 64 + o];
    const float R = 0.70710678118654752f;
    float v[8];
    v[0] = w;
    v[1] = c1;
    v[2] = R * (c2 + c3);
    v[3] = R * (c2 - c3);
    v[4] = 0.5f * (c4 + c5 + c6 + c7);
    v[5] = 0.5f * (c4 - c5 + c6 - c7);
    v[6] = 0.5f * (c4 + c5 - c6 - c7);
    v[7] = 0.5f * (c4 - c5 - c6 + c7);
    unsigned p[4];
#pragma unroll
    for (int i = 0; i < 4; i++) {
        unsigned lo = (unsigned)__half_as_ushort(__float2half(v[2 * i]));
        unsigned hi = (unsigned)__half_as_ushort(__float2half(v[2 * i + 1]));
        p[i] = lo | (hi << 16);
    }
    uint4 pk; pk.x = p[0]; pk.y = p[1]; pk.z = p[2]; pk.w = p[3];
    int kt = f >> 3, fl = f & 7;
    g_B4[kt * 512 + o * 8 + fl] = pk;
}

// ---------------------------------------------------------------------------
// Prologue 2: bias[o] = sum_f coeffs[f,o,0]   (deterministic tree reduce)
// ---------------------------------------------------------------------------
__global__ void wb_prep_bias(const float* __restrict__ coeffs) {
    __shared__ float red[128];
    int o = blockIdx.x;
    int t = threadIdx.x;
    float s = 0.f;
    for (int f = t; f < FDIM; f += 128)
        s += coeffs[(size_t)(f * 64 + o) * 8];
    red[t] = s;
    __syncthreads();
#pragma unroll
    for (int st = 64; st > 0; st >>= 1) {
        if (t < st) red[t] += red[t + st];
        __syncthreads();
    }
    if (t == 0) g_bias[o] = red[0];
}

// ---------------------------------------------------------------------------
// Main GEMM: 256 CTAs x 128 threads. CTA tile: M=128 rows, N=64, K streamed.
// Warp (4 per CTA) handles 32 rows: two m16 groups, 8 n8 blocks.
// A generated in smem each chunk; B chunk copied from g_B4.
// FP16 accumulators within a chunk, promoted to fp32 per chunk.
// ---------------------------------------------------------------------------
#define LDMX4(R, ADDR)                                                        \
    asm volatile("ldmatrix.sync.aligned.m8n8.x4.shared.b16 {%0,%1,%2,%3}, [%4];" \
                 : "=r"((R)[0]), "=r"((R)[1]), "=r"((R)[2]), "=r"((R)[3])     \
                 : "r"(ADDR))
#define LDMX2(R, ADDR)                                                        \
    asm volatile("ldmatrix.sync.aligned.m8n8.x2.shared.b16 {%0,%1}, [%2];"    \
                 : "=r"((R)[0]), "=r"((R)[1])                                 \
                 : "r"(ADDR))
#define MMA16816H(C, A, B)                                                    \
    asm volatile("mma.sync.aligned.m16n8k16.row.col.f16.f16.f16.f16 "         \
                 "{%0,%1}, {%2,%3,%4,%5}, {%6,%7}, {%0,%1};"                  \
                 : "+r"((C)[0]), "+r"((C)[1])                                 \
                 : "r"((A)[0]), "r"((A)[1]), "r"((A)[2]), "r"((A)[3]),        \
                   "r"((B)[0]), "r"((B)[1]))

__global__ void __launch_bounds__(128)
wb_main(const float* __restrict__ x, float* __restrict__ out, int out_size) {
    __shared__ __half As[128][72];   // padded stride (144 B): bank-conflict-free
    __shared__ __half Bs[64][72];

    const int t = threadIdx.x;
    const int w = t >> 5;
    const int l = t & 31;
    const int bx = blockIdx.x;

    float acc[2][8][4];
#pragma unroll
    for (int g = 0; g < 2; g++)
#pragma unroll
        for (int nb = 0; nb < 8; nb++)
#pragma unroll
            for (int i = 0; i < 4; i++) acc[g][nb][i] = 0.f;

    // Precompute ldmatrix shared addresses (stride constant within loop)
    const int li = l & 15;
    uint32_t a_addr0 = (uint32_t)__cvta_generic_to_shared(
        &As[w * 32 + (l & 15)][(l >> 4) * 8]);
    uint32_t a_addr1 = (uint32_t)__cvta_generic_to_shared(
        &As[w * 32 + 16 + (l & 15)][(l >> 4) * 8]);
    uint32_t b_addr0 = (uint32_t)__cvta_generic_to_shared(
        &Bs[(li & 7)][(li >> 3) * 8]);

    for (int kt = 0; kt < NCHUNK; kt++) {
        __syncthreads();  // previous compute done before overwriting tiles

        // ---- generate A chunk: rows 0..127, 8 features (k_local 0..63) ----
#pragma unroll
        for (int j = 0; j < 2; j++) {
            int id = t + j * 128;           // 256 float4 loads total
            int row = id >> 1, half = id & 1;
            const float4 xv = *(const float4*)(
                x + (size_t)(bx * 128 + row) * FDIM + kt * 8 + half * 4);
            float xa[4] = {xv.x, xv.y, xv.z, xv.w};
#pragma unroll
            for (int i = 0; i < 4; i++) {
                float xs = xa[i];
                bool b2 = xs >= 0.0f;
                bool b1 = xs >= (b2 ? T6 : T2);
                bool b0 = xs >= (b2 ? (b1 ? T7 : T5) : (b1 ? T3 : T1));
                unsigned s0 = b2 ? 0x8000u : 0u;
                unsigned s1 = b1 ? 0x8000u : 0u;
                unsigned s2 = b0 ? 0x8000u : 0u;
                const unsigned ONE = 0x3C00u;
                unsigned hx = (unsigned)__half_as_ushort(__float2half(xs));
                uint4 pk;
                pk.x = hx | ((ONE | s0) << 16);
                pk.y = (ONE | s1) | ((ONE | (s0 ^ s1)) << 16);
                pk.z = (ONE | s2) | ((ONE | (s1 ^ s2)) << 16);
                pk.w = (ONE | (s0 ^ s2)) | ((ONE | (s0 ^ s1 ^ s2)) << 16);
                *(uint4*)&As[row][(half * 4 + i) * 8] = pk;
            }
        }

        // ---- copy B chunk: 512 uint4 (64 n x 64 k halves) ----
#pragma unroll
        for (int j = 0; j < 4; j++) {
            int id = t + j * 128;
            int n = id >> 3, kp = id & 7;
            *(uint4*)&Bs[n][kp * 8] = g_B4[(kt * 64 + n) * 8 + kp];
        }

        __syncthreads();

        // ---- compute: 4 k16 steps, fp16 accumulators for this chunk ----
        uint32_t hacc[2][8][2];
#pragma unroll
        for (int g = 0; g < 2; g++)
#pragma unroll
            for (int nb = 0; nb < 8; nb++) {
                hacc[g][nb][0] = 0u;
                hacc[g][nb][1] = 0u;
            }

#pragma unroll
        for (int ks = 0; ks < 4; ks++) {
            const uint32_t koff = (uint32_t)(ks * 32);  // 16 halves = 32 bytes
            uint32_t a0[4], a1[4];
            LDMX4(a0, a_addr0 + koff);
            LDMX4(a1, a_addr1 + koff);
            uint32_t bf[8][2];
#pragma unroll
            for (int nb = 0; nb < 8; nb++)
                LDMX2(bf[nb], b_addr0 + (uint32_t)(nb * 8 * 144) + koff);
#pragma unroll
            for (int nb = 0; nb < 8; nb++) {
                MMA16816H(hacc[0][nb], a0, bf[nb]);
                MMA16816H(hacc[1][nb], a1, bf[nb]);
            }
        }

        // ---- promote chunk partials to fp32 ----
#pragma unroll
        for (int g = 0; g < 2; g++)
#pragma unroll
            for (int nb = 0; nb < 8; nb++) {
                float2 p0 = __half22float2(*(__half2*)&hacc[g][nb][0]);
                float2 p1 = __half22float2(*(__half2*)&hacc[g][nb][1]);
                acc[g][nb][0] += p0.x;
                acc[g][nb][1] += p0.y;
                acc[g][nb][2] += p1.x;
                acc[g][nb][3] += p1.y;
            }
    }

    // ---- epilogue: add bias, store fp32 ----
    const int col0 = (l & 3) * 2;
    float2 bias2[8];
#pragma unroll
    for (int nb = 0; nb < 8; nb++)
        bias2[nb] = *(const float2*)&g_bias[nb * 8 + col0];

#pragma unroll
    for (int g = 0; g < 2; g++) {
        int row0 = bx * 128 + w * 32 + g * 16 + (l >> 2);
#pragma unroll
        for (int nb = 0; nb < 8; nb++) {
            float2 v0, v1;
            v0.x = acc[g][nb][0] + bias2[nb].x;
            v0.y = acc[g][nb][1] + bias2[nb].y;
            v1.x = acc[g][nb][2] + bias2[nb].x;
            v1.y = acc[g][nb][3] + bias2[nb].y;
            *(float2*)(out + (size_t)row0 * 64 + nb * 8 + col0) = v0;
            *(float2*)(out + (size_t)(row0 + 8) * 64 + nb * 8 + col0) = v1;
        }
    }

    // kl output (zeros) — tail elements past the [B,O] block
    if (bx == 0 && t == 0) {
        for (int i = OUT_ELEMS; i < out_size; i++) out[i] = 0.f;
    }
}

// ---------------------------------------------------------------------------
extern "C" void kernel_launch(void* const* d_in, const int* in_sizes, int n_in,
                              void* d_out, int out_size) {
    const float* x      = (const float*)d_in[0];   // [32768,1024] f32
    const float* coeffs = (const float*)d_in[1];   // [1024,64,8] f32
    const float* bw     = (const float*)d_in[2];   // [1024,64] f32
    float* out = (float*)d_out;

    wb_prep_B<<<512, 128>>>(coeffs, bw);
    wb_prep_bias<<<64, 128>>>(coeffs);
    wb_main<<<256, 128>>>(x, out, out_size);
}

// round 11
// speedup vs baseline: 1.3751x; 1.3751x over previous
#include <cuda_runtime.h>
#include <cuda_fp16.h>
#include <cstdint>
#include <cstddef>

// ============================================================================
// WaveletBasis: out[B,O] = haar_basis(x).coeffs + x @ base_weight ; kl = 0
//   B=32768, F=1024, O=64, NB=8
// One fp16 GEMM (fp32 accum) on mma.sync HMMA (tcgen05 rejected by harness
// ptxas targeting sm_103 without 'a'):
//   out = A[B,8192] * Bm[8192,64] + bias
// Per feature f (8 K-slots), j = clip(floor(8u),0,7), u=(tanh x+1)/2:
//   A slots = [x, s0, s1, s0s1, s2, s1s2, s0s2, s0s1s2]  (signs from bits of j)
//   Bm rows = [bw, c1, R(c2+c3), R(c2-c3), H4-rotated c4..c7 / 2], R=sqrt2/2
//   bias[o] = sum_f coeffs[f,o,0]
// j computed WITHOUT tanh: u >= i/8  <=>  x >= atanh(i/4 - 1).
//
// R10 change: K-SPLIT 4 for occupancy (1024 CTAs instead of 256). Each CTA
// accumulates 32 of 128 K-chunks into a deterministic partial buffer; a
// reduce kernel sums the 4 partials + bias. Work totals unchanged; latency
// exposure (the R4-R9 binder) divided by ~4x resident-warp increase.
// ============================================================================

static constexpr int FDIM = 1024;
static constexpr int NCHUNK = 128;           // K chunks of 64 (8 features)
static constexpr int NSPLIT = 4;
static constexpr int CH_PER = NCHUNK / NSPLIT;   // 32 chunks per CTA
static constexpr int OUT_ELEMS = 32768 * 64;

#define T1 (-0.9729550745276566f)
#define T2 (-0.5493061443340548f)
#define T3 (-0.2554128118829953f)
#define T5 ( 0.2554128118829953f)
#define T6 ( 0.5493061443340548f)
#define T7 ( 0.9729550745276566f)

// B operand fp16, linear chunk layout: [kt=128][n=64][kp=8] uint4 = 1 MB
__device__ uint4 g_B4[NCHUNK * 512];
__device__ float g_bias[64];
// K-split partial sums: [split][B*O] fp32 = 32 MB scratch
__device__ float g_part[NSPLIT * OUT_ELEMS];

// ---------------------------------------------------------------------------
// Prologue 1: rotated B matrix (fp16)
// ---------------------------------------------------------------------------
__global__ void wb_prep_B(const float* __restrict__ coeffs,
                          const float* __restrict__ bw) {
    int gid = blockIdx.x * blockDim.x + threadIdx.x;   // 65536 = F*O
    int f = gid >> 6;
    int o = gid & 63;
    const float* c = coeffs + (size_t)(f * 64 + o) * 8;
    float c1 = c[1], c2 = c[2], c3 = c[3];
    float c4 = c[4], c5 = c[5], c6 = c[6], c7 = c[7];
    float w = bw[f * 64 + o];
    const float R = 0.70710678118654752f;
    float v[8];
    v[0] = w;
    v[1] = c1;
    v[2] = R * (c2 + c3);
    v[3] = R * (c2 - c3);
    v[4] = 0.5f * (c4 + c5 + c6 + c7);
    v[5] = 0.5f * (c4 - c5 + c6 - c7);
    v[6] = 0.5f * (c4 + c5 - c6 - c7);
    v[7] = 0.5f * (c4 - c5 - c6 + c7);
    unsigned p[4];
#pragma unroll
    for (int i = 0; i < 4; i++) {
        unsigned lo = (unsigned)__half_as_ushort(__float2half(v[2 * i]));
        unsigned hi = (unsigned)__half_as_ushort(__float2half(v[2 * i + 1]));
        p[i] = lo | (hi << 16);
    }
    uint4 pk; pk.x = p[0]; pk.y = p[1]; pk.z = p[2]; pk.w = p[3];
    int kt = f >> 3, fl = f & 7;
    g_B4[kt * 512 + o * 8 + fl] = pk;
}

// ---------------------------------------------------------------------------
// Prologue 2: bias[o] = sum_f coeffs[f,o,0]   (deterministic tree reduce)
// ---------------------------------------------------------------------------
__global__ void wb_prep_bias(const float* __restrict__ coeffs) {
    __shared__ float red[128];
    int o = blockIdx.x;
    int t = threadIdx.x;
    float s = 0.f;
    for (int f = t; f < FDIM; f += 128)
        s += coeffs[(size_t)(f * 64 + o) * 8];
    red[t] = s;
    __syncthreads();
#pragma unroll
    for (int st = 64; st > 0; st >>= 1) {
        if (t < st) red[t] += red[t + st];
        __syncthreads();
    }
    if (t == 0) g_bias[o] = red[0];
}

// ---------------------------------------------------------------------------
// Main GEMM: 1024 CTAs x 128 threads. CTA = (tile, split):
//   tile = bx & 255 -> rows tile*128..+128 ; split = bx >> 8 -> chunks
//   split*32..+32. Warp handles 32 rows (two m16 groups) x N=64.
// ---------------------------------------------------------------------------
#define LDMX4(R, ADDR)                                                        \
    asm volatile("ldmatrix.sync.aligned.m8n8.x4.shared.b16 {%0,%1,%2,%3}, [%4];" \
                 : "=r"((R)[0]), "=r"((R)[1]), "=r"((R)[2]), "=r"((R)[3])     \
                 : "r"(ADDR))
#define MMA16816(C, A, B0, B1)                                                \
    asm volatile("mma.sync.aligned.m16n8k16.row.col.f32.f16.f16.f32 "         \
                 "{%0,%1,%2,%3}, {%4,%5,%6,%7}, {%8,%9}, {%0,%1,%2,%3};"      \
                 : "+f"((C)[0]), "+f"((C)[1]), "+f"((C)[2]), "+f"((C)[3])     \
                 : "r"((A)[0]), "r"((A)[1]), "r"((A)[2]), "r"((A)[3]),        \
                   "r"(B0), "r"(B1))

__global__ void __launch_bounds__(128, 4)
wb_main(const float* __restrict__ x) {
    __shared__ __half As[128][72];   // padded 144 B stride: conflict-free
    __shared__ __half Bs[64][72];

    const int t = threadIdx.x;
    const int w = t >> 5;
    const int l = t & 31;
    const int tile  = blockIdx.x & 255;
    const int split = blockIdx.x >> 8;
    const int kt0 = split * CH_PER;

    float acc[2][8][4];
#pragma unroll
    for (int g = 0; g < 2; g++)
#pragma unroll
        for (int nb = 0; nb < 8; nb++)
#pragma unroll
            for (int i = 0; i < 4; i++) acc[g][nb][i] = 0.f;

    // A fragment addresses (verified R4 mapping)
    uint32_t a_addr0 = (uint32_t)__cvta_generic_to_shared(
        &As[w * 32 + (l & 15)][(l >> 4) * 8]);
    uint32_t a_addr1 = (uint32_t)__cvta_generic_to_shared(
        &As[w * 32 + 16 + (l & 15)][(l >> 4) * 8]);
    // B fragment addresses via x4 n-pairs (verified R7 mapping)
    const uint32_t bs_base = (uint32_t)__cvta_generic_to_shared(&Bs[0][0]);
    uint32_t b_off[4];
#pragma unroll
    for (int p = 0; p < 4; p++)
        b_off[p] = bs_base + (uint32_t)((p * 16 + ((l >> 4) << 3) + (l & 7)) * 144 +
                                        ((l >> 3) & 1) * 16);

    for (int ki = 0; ki < CH_PER; ki++) {
        const int kt = kt0 + ki;
        __syncthreads();  // previous compute done before overwriting tiles

        // ---- generate A chunk: rows 0..127, 8 features ----
#pragma unroll
        for (int j = 0; j < 2; j++) {
            int id = t + j * 128;
            int row = id >> 1, half = id & 1;
            const float4 xv = *(const float4*)(
                x + (size_t)(tile * 128 + row) * FDIM + kt * 8 + half * 4);
            float xa[4] = {xv.x, xv.y, xv.z, xv.w};
#pragma unroll
            for (int i = 0; i < 4; i++) {
                float xs = xa[i];
                bool b2 = xs >= 0.0f;
                bool b1 = xs >= (b2 ? T6 : T2);
                bool b0 = xs >= (b2 ? (b1 ? T7 : T5) : (b1 ? T3 : T1));
                unsigned s0 = b2 ? 0x8000u : 0u;
                unsigned s1 = b1 ? 0x8000u : 0u;
                unsigned s2 = b0 ? 0x8000u : 0u;
                const unsigned ONE = 0x3C00u;
                unsigned hx = (unsigned)__half_as_ushort(__float2half(xs));
                uint4 pk;
                pk.x = hx | ((ONE | s0) << 16);
                pk.y = (ONE | s1) | ((ONE | (s0 ^ s1)) << 16);
                pk.z = (ONE | s2) | ((ONE | (s1 ^ s2)) << 16);
                pk.w = (ONE | (s0 ^ s2)) | ((ONE | (s0 ^ s1 ^ s2)) << 16);
                *(uint4*)&As[row][(half * 4 + i) * 8] = pk;
            }
        }

        // ---- copy B chunk: 512 uint4 ----
#pragma unroll
        for (int j = 0; j < 4; j++) {
            int id = t + j * 128;
            int n = id >> 3, kp = id & 7;
            *(uint4*)&Bs[n][kp * 8] = g_B4[(kt * 64 + n) * 8 + kp];
        }

        __syncthreads();

        // ---- compute: 4 k16 steps ----
#pragma unroll
        for (int ks = 0; ks < 4; ks++) {
            const uint32_t koff = (uint32_t)(ks * 32);
            uint32_t a0[4], a1[4], bf[4][4];
            LDMX4(a0, a_addr0 + koff);
            LDMX4(a1, a_addr1 + koff);
#pragma unroll
            for (int p = 0; p < 4; p++) LDMX4(bf[p], b_off[p] + koff);
#pragma unroll
            for (int p = 0; p < 4; p++) {
                MMA16816(acc[0][2 * p],     a0, bf[p][0], bf[p][1]);
                MMA16816(acc[1][2 * p],     a1, bf[p][0], bf[p][1]);
                MMA16816(acc[0][2 * p + 1], a0, bf[p][2], bf[p][3]);
                MMA16816(acc[1][2 * p + 1], a1, bf[p][2], bf[p][3]);
            }
        }
    }

    // ---- epilogue: store fp32 partials (no bias here) ----
    float* part = g_part + (size_t)split * OUT_ELEMS;
    const int col0 = (l & 3) * 2;
#pragma unroll
    for (int g = 0; g < 2; g++) {
        int row0 = tile * 128 + w * 32 + g * 16 + (l >> 2);
#pragma unroll
        for (int nb = 0; nb < 8; nb++) {
            float2 v0, v1;
            v0.x = acc[g][nb][0];
            v0.y = acc[g][nb][1];
            v1.x = acc[g][nb][2];
            v1.y = acc[g][nb][3];
            *(float2*)(part + (size_t)row0 * 64 + nb * 8 + col0) = v0;
            *(float2*)(part + (size_t)(row0 + 8) * 64 + nb * 8 + col0) = v1;
        }
    }
}

// ---------------------------------------------------------------------------
// Reduce: out = sum(partials) + bias ; zero kl tail
// ---------------------------------------------------------------------------
__global__ void wb_reduce(float* __restrict__ out, int out_size) {
    int i = blockIdx.x * blockDim.x + threadIdx.x;   // float4 index
    const float4* p = (const float4*)g_part;
    float4 v0 = p[i];
    float4 v1 = p[i + OUT_ELEMS / 4];
    float4 v2 = p[i + 2 * (OUT_ELEMS / 4)];
    float4 v3 = p[i + 3 * (OUT_ELEMS / 4)];
    const float4 bv = *(const float4*)&g_bias[(i * 4) & 63];
    float4 r;
    r.x = (v0.x + v1.x) + (v2.x + v3.x) + bv.x;
    r.y = (v0.y + v1.y) + (v2.y + v3.y) + bv.y;
    r.z = (v0.z + v1.z) + (v2.z + v3.z) + bv.z;
    r.w = (v0.w + v1.w) + (v2.w + v3.w) + bv.w;
    ((float4*)out)[i] = r;
    if (blockIdx.x == 0 && threadIdx.x == 0) {
        for (int k = OUT_ELEMS; k < out_size; k++) out[k] = 0.f;
    }
}

// ---------------------------------------------------------------------------
extern "C" void kernel_launch(void* const* d_in, const int* in_sizes, int n_in,
                              void* d_out, int out_size) {
    const float* x      = (const float*)d_in[0];   // [32768,1024] f32
    const float* coeffs = (const float*)d_in[1];   // [1024,64,8]  f32
    const float* bw     = (const float*)d_in[2];   // [1024,64]    f32
    float* out = (float*)d_out;

    wb_prep_B<<<512, 128>>>(coeffs, bw);
    wb_prep_bias<<<64, 128>>>(coeffs);
    wb_main<<<256 * NSPLIT, 128>>>(x);
    wb_reduce<<<OUT_ELEMS / 4 / 256, 256>>>(out, out_size);
}